// round 14
// baseline (speedup 1.0000x reference)
#include <cuda_runtime.h>
#include <cuda_fp16.h>
#include <cstdint>

#define Bn 32768
#define Kn 8192
#define Dn 512
#define DECAYF 0.99f
#define OMDF   0.01f
#define EPSF   1e-5f

#define NITER 8              // K=512, BLK_K=64
#define STB 18432            // bytes per stage: 128 rows * 144B
#define SM_CSQ  110592       // after 3*STB*2
#define SMEM_BYTES 111104

// Device scratch (allocation-free). NEVER referenced from host code.
__device__ uint4  g_A4[(size_t)Bn * Dn * 2 / 16];     // fp16 of z_e
__device__ uint4  g_B4[(size_t)Kn * Dn * 2 / 16];     // fp16 of codebook
__device__ unsigned char g_scores8[(size_t)Bn * Kn];  // u8 score codes (step 2.0)
__device__ float  g_embed[(size_t)Kn * Dn];
__device__ float  g_counts[Kn];
__device__ float  g_csq[Kn];
__device__ unsigned g_cmax_bits;                      // max csq (float bits)

__device__ __forceinline__ uint32_t smem_u32(const void* p) {
    uint32_t a;
    asm("{ .reg .u64 t; cvta.to.shared.u64 t, %1; cvt.u32.u64 %0, t; }"
        : "=r"(a) : "l"(p));
    return a;
}
__device__ __forceinline__ void cpa16(uint32_t s, const void* g) {
    asm volatile("cp.async.cg.shared.global [%0], [%1], 16;" :: "r"(s), "l"(g));
}
#define CP_COMMIT() asm volatile("cp.async.commit_group;" ::: "memory")
#define CP_WAIT1()  asm volatile("cp.async.wait_group 1;" ::: "memory")

__device__ __forceinline__ void ldsm4(uint32_t& r0, uint32_t& r1, uint32_t& r2,
                                      uint32_t& r3, uint32_t addr) {
    asm volatile("ldmatrix.sync.aligned.m8n8.x4.shared.b16 {%0,%1,%2,%3}, [%4];"
                 : "=r"(r0), "=r"(r1), "=r"(r2), "=r"(r3) : "r"(addr));
}
// fp16-accumulator HMMA: D,C are 2x b32 (4 halves)
__device__ __forceinline__ void hmma16(uint32_t* c, uint32_t a0, uint32_t a1,
                                       uint32_t a2, uint32_t a3,
                                       uint32_t b0, uint32_t b1) {
    asm volatile(
        "mma.sync.aligned.m16n8k16.row.col.f16.f16.f16.f16 "
        "{%0,%1}, {%2,%3,%4,%5}, {%6,%7}, {%0,%1};"
        : "+r"(c[0]), "+r"(c[1])
        : "r"(a0), "r"(a1), "r"(a2), "r"(a3), "r"(b0), "r"(b1));
}
__device__ __forceinline__ unsigned f2ord(float f) {
    unsigned u = __float_as_uint(f);
    return (u & 0x80000000u) ? ~u : (u | 0x80000000u);
}
__device__ __forceinline__ void st_u16_cs(void* p, unsigned short v) {
    asm volatile("st.global.cs.u16 [%0], %1;" :: "l"(p), "h"(v) : "memory");
}

// ---------------------------------------------------------------------------
// z_e fp32 -> fp16 conversion, FUSED with scratch zeroing
__global__ void splitA_zero_kernel(const float* __restrict__ src) {
    ushort4* dst = (ushort4*)(void*)g_A4;
    int stride = gridDim.x * blockDim.x;
    int t0 = blockIdx.x * blockDim.x + threadIdx.x;
    const int n4 = Bn * Dn / 4;
    for (int i = t0; i < n4; i += stride) {
        float4 v = ((const float4*)src)[i];
        __half2 lo = __floats2half2_rn(v.x, v.y);
        __half2 hi = __floats2half2_rn(v.z, v.w);
        ushort4 o;
        o.x = *(unsigned short*)&lo;  o.y = ((unsigned short*)&lo)[1];
        o.z = *(unsigned short*)&hi;  o.w = ((unsigned short*)&hi)[1];
        dst[i] = o;
    }
    const int N = Kn * Dn;
    for (int i = t0; i < N; i += stride) g_embed[i] = 0.0f;
    if (t0 < Kn) g_counts[t0] = 0.0f;
    if (t0 == 0) g_cmax_bits = 0u;
}

// codebook fp32 -> fp16 AND csq, one warp per row
__global__ void splitB_csq_kernel(const float* __restrict__ cb) {
    int warp = (blockIdx.x * blockDim.x + threadIdx.x) >> 5;
    int lane = threadIdx.x & 31;
    if (warp >= Kn) return;
    const float4* row = (const float4*)(cb + (size_t)warp * Dn);
    ushort4* drow = (ushort4*)((__half*)(void*)g_B4 + (size_t)warp * Dn);
    float s = 0.0f;
    #pragma unroll
    for (int i = lane; i < Dn / 4; i += 32) {
        float4 v = row[i];
        s += v.x * v.x + v.y * v.y + v.z * v.z + v.w * v.w;
        __half2 lo = __floats2half2_rn(v.x, v.y);
        __half2 hi = __floats2half2_rn(v.z, v.w);
        ushort4 o;
        o.x = *(unsigned short*)&lo;  o.y = ((unsigned short*)&lo)[1];
        o.z = *(unsigned short*)&hi;  o.w = ((unsigned short*)&hi)[1];
        drow[i] = o;
    }
    #pragma unroll
    for (int o = 16; o > 0; o >>= 1) s += __shfl_xor_sync(0xFFFFFFFFu, s, o);
    if (lane == 0) {
        g_csq[warp] = s;
        atomicMax(&g_cmax_bits, __float_as_uint(s));
    }
}

// ---------------------------------------------------------------------------
// Pass 1: fp16 GEMM (fp16 accumulate), u8 score codes streamed to g_scores8.
// Block 128x128, 8 warps (4x2), warp tile 32x64, BLK_K=64, 3-slot cp.async.
// (exact R12 mainloop — measured 865us, at the legacy-HMMA issue floor)
// ---------------------------------------------------------------------------
__global__ void __launch_bounds__(256, 2)
gemm_kernel() {
    extern __shared__ char sm[];
    const uint32_t sA = smem_u32(sm);
    const uint32_t sB = sA + 3 * STB;
    float* csq_s = (float*)(sm + SM_CSQ);

    const int tid = threadIdx.x;
    const int lane = tid & 31;
    const int w = tid >> 5;
    const int warpM = w & 3;
    const int warpN = w >> 2;
    const int rowBase = (blockIdx.x >> 6) * 128;
    const int colBase = (blockIdx.x & 63) * 128;   // colTile-fastest: B L2-resident

    if (tid < 128) csq_s[tid] = g_csq[colBase + tid];

    const __half* A = (const __half*)(void*)g_A4;
    const __half* Bm = (const __half*)(void*)g_B4;

    const int lr = tid >> 3, lc = tid & 7;
    const uint32_t soBase = (uint32_t)(lr * 144 + lc * 16);
    const __half* gA = A + (size_t)(rowBase + lr) * Dn + lc * 8;
    const __half* gB = Bm + (size_t)(colBase + lr) * Dn + lc * 8;

    uint32_t acc[2][8][2];                 // fp16x2 accumulators
    #pragma unroll
    for (int mt = 0; mt < 2; mt++)
        #pragma unroll
        for (int nt = 0; nt < 8; nt++) { acc[mt][nt][0] = 0u; acc[mt][nt][1] = 0u; }

    const int lrow = lane & 15;
    const int khalf = lane >> 4;
    const uint32_t aRowOff = (uint32_t)((warpM * 32 + lrow) * 144 + khalf * 16);
    const uint32_t bRowOff = (uint32_t)((warpN * 64 + lrow) * 144 + khalf * 16);

    #define LOAD_STAGE(s, slot) do {                                           \
        int _off = (s) << 6;                                                   \
        uint32_t _da = sA + (slot) * STB;                                      \
        uint32_t _db = sB + (slot) * STB;                                      \
        _Pragma("unroll")                                                      \
        for (int it = 0; it < 4; it++) {                                       \
            uint32_t so = soBase + it * 32 * 144;                              \
            cpa16(_da + so, gA + (size_t)(it * 32) * Dn + _off);               \
            cpa16(_db + so, gB + (size_t)(it * 32) * Dn + _off);               \
        }                                                                      \
    } while (0)

    LOAD_STAGE(0, 0); CP_COMMIT();
    LOAD_STAGE(1, 1); CP_COMMIT();

    int slot = 0, nslot = 2;
    #pragma unroll 1
    for (int s = 0; s < NITER; s++) {
        CP_WAIT1();
        __syncthreads();
        if (s + 2 < NITER) LOAD_STAGE(s + 2, nslot);
        CP_COMMIT();

        const uint32_t da = sA + slot * STB;
        const uint32_t db = sB + slot * STB;
        #pragma unroll
        for (int k16 = 0; k16 < 4; k16++) {
            uint32_t a[2][4];
            #pragma unroll
            for (int mt = 0; mt < 2; mt++)
                ldsm4(a[mt][0], a[mt][1], a[mt][2], a[mt][3],
                      da + aRowOff + mt * 16 * 144 + k16 * 32);
            uint32_t b[4][4];
            #pragma unroll
            for (int np = 0; np < 4; np++)
                ldsm4(b[np][0], b[np][1], b[np][2], b[np][3],
                      db + bRowOff + np * 16 * 144 + k16 * 32);
            #pragma unroll
            for (int mt = 0; mt < 2; mt++)
                #pragma unroll
                for (int nt = 0; nt < 8; nt++)
                    hmma16(acc[mt][nt],
                           a[mt][0], a[mt][1], a[mt][2], a[mt][3],
                           b[nt >> 1][(nt & 1) ? 1 : 0],
                           b[nt >> 1][(nt & 1) ? 3 : 2]);
        }
        slot = slot == 2 ? 0 : slot + 1;
        nslot = nslot == 2 ? 0 : nslot + 1;
    }
    #undef LOAD_STAGE

    // epilogue: u8 code = clamp(round((csq - 2*dot)/2), 0, 255), streamed.
    const int g = lane >> 2, tg = lane & 3;
    #pragma unroll
    for (int mt = 0; mt < 2; mt++) {
        #pragma unroll
        for (int half = 0; half < 2; half++) {
            int grow = rowBase + warpM * 32 + mt * 16 + half * 8 + g;
            unsigned char* dst = g_scores8 + (size_t)grow * Kn + colBase;
            #pragma unroll
            for (int nt = 0; nt < 8; nt++) {
                int cl = warpN * 64 + nt * 8 + tg * 2;
                float2 f = __half22float2(*(const __half2*)&acc[mt][nt][half]);
                float s0 = fmaf(-2.0f, f.x, csq_s[cl]);
                float s1 = fmaf(-2.0f, f.y, csq_s[cl + 1]);
                int q0 = __float2int_rn(s0 * 0.5f);
                int q1 = __float2int_rn(s1 * 0.5f);
                q0 = min(255, max(0, q0));
                q1 = min(255, max(0, q1));
                st_u16_cs(dst + cl, (unsigned short)(q0 | (q1 << 8)));
            }
        }
    }
}

// ---------------------------------------------------------------------------
// Pass 2 (fused with scatter): u8 SIMD scan, exact fp32 rescore of candidates,
// write z_q + indices, atomic scatter counts/embed. One 256-thread block/row.
// ---------------------------------------------------------------------------
#define MAXCAND 128
__global__ void __launch_bounds__(256)
select_kernel(const float* __restrict__ z_e, const float* __restrict__ cb,
              float* __restrict__ out) {
    __shared__ float zs[Dn];
    __shared__ float rz[8];
    __shared__ int rsI[8];
    __shared__ int list[MAXCAND];
    __shared__ int cnt;
    __shared__ int thrS;
    __shared__ unsigned long long bestPk;

    const int row = blockIdx.x;
    const int t = threadIdx.x;
    const int lane = t & 31, wid = t >> 5;

    float2 zv = ((const float2*)(z_e + (size_t)row * Dn))[t];
    ((float2*)zs)[t] = zv;
    float zp = zv.x * zv.x + zv.y * zv.y;
    #pragma unroll
    for (int o = 16; o > 0; o >>= 1) zp += __shfl_xor_sync(0xFFFFFFFFu, zp, o);
    if (lane == 0) rz[wid] = zp;
    if (t == 0) { cnt = 0; bestPk = 0xFFFFFFFFFFFFFFFFull; }

    // load 32 u8 scores via 2 uint4 (evict-first), SIMD min
    const uint4* sr = (const uint4*)(g_scores8 + (size_t)row * Kn);
    uint4 sv[2];
    unsigned mn4 = 0xFFFFFFFFu;
    #pragma unroll
    for (int i = 0; i < 2; i++) {
        sv[i] = __ldcs(sr + t + (i << 8));
        mn4 = __vminu4(mn4, sv[i].x);
        mn4 = __vminu4(mn4, sv[i].y);
        mn4 = __vminu4(mn4, sv[i].z);
        mn4 = __vminu4(mn4, sv[i].w);
    }
    mn4 = __vminu4(mn4, mn4 >> 16);
    mn4 = __vminu4(mn4, mn4 >> 8);
    int mn = (int)(mn4 & 0xFFu);
    #pragma unroll
    for (int o = 16; o > 0; o >>= 1) mn = min(mn, __shfl_xor_sync(0xFFFFFFFFu, mn, o));
    if (lane == 0) rsI[wid] = mn;
    __syncthreads();
    if (t == 0) {
        float zsq = 0.0f;
        int m = 255;
        #pragma unroll
        for (int i = 0; i < 8; i++) { zsq += rz[i]; m = min(m, rsI[i]); }
        float cmax = __uint_as_float(g_cmax_bits);
        // margin (float) = h0 bound + fp16-acc slack; +2 units for u8 rounding
        float E = 0.001953125f * sqrtf(zsq * cmax) + 16.0f;
        thrS = m + (int)ceilf(E * 0.5f) + 2;
    }
    __syncthreads();

    const int thrU = thrS;
    if (thrU <= 254) {
        const unsigned thrPack = (unsigned)thrU * 0x01010101u;
        #pragma unroll
        for (int i = 0; i < 2; i++) {
            const unsigned* uw = (const unsigned*)&sv[i];
            #pragma unroll
            for (int wv = 0; wv < 4; wv++) {
                unsigned mask = __vcmpleu4(uw[wv], thrPack);
                if (mask) {
                    int base = (i << 12) + t * 16 + wv * 4;
                    #pragma unroll
                    for (int j = 0; j < 4; j++) {
                        if (mask & (0xFFu << (8 * j))) {
                            int p = atomicAdd(&cnt, 1);
                            if (p < MAXCAND) list[p] = base + j;
                        }
                    }
                }
            }
        }
        __syncthreads();
    } else {
        if (t == 0) cnt = MAXCAND + 1;     // force brute-force fallback
        __syncthreads();
    }

    if (cnt <= MAXCAND) {
        const int n = cnt;
        for (int j = wid; j < n; j += 8) {
            const int k = list[j];
            const float4* crow = (const float4*)(cb + (size_t)k * Dn);
            const float4* zrow = (const float4*)zs;
            float d = 0.0f;
            #pragma unroll
            for (int c = lane; c < Dn / 4; c += 32) {
                float4 aa = zrow[c], bb = crow[c];
                d += aa.x * bb.x + aa.y * bb.y + aa.z * bb.z + aa.w * bb.w;
            }
            #pragma unroll
            for (int o = 16; o > 0; o >>= 1) d += __shfl_xor_sync(0xFFFFFFFFu, d, o);
            if (lane == 0) {
                float ex = fmaf(-2.0f, d, g_csq[k]);
                unsigned long long pk =
                    ((unsigned long long)f2ord(ex) << 32) | (unsigned)k;
                atomicMin(&bestPk, pk);
            }
        }
    } else {
        // pathological overflow: exact brute force (sound fallback)
        for (int k = t; k < Kn; k += 256) {
            const float* crow = cb + (size_t)k * Dn;
            float d = 0.0f;
            for (int c = 0; c < Dn; c++) d += zs[c] * crow[c];
            float ex = fmaf(-2.0f, d, g_csq[k]);
            unsigned long long pk =
                ((unsigned long long)f2ord(ex) << 32) | (unsigned)k;
            atomicMin(&bestPk, pk);
        }
    }
    __syncthreads();

    const int idx = (int)(unsigned)(bestPk & 0xFFFFFFFFull);
    float2 cq = ((const float2*)(cb + (size_t)idx * Dn))[t];
    ((float2*)(out + (size_t)row * Dn))[t] = cq;       // z_q
    float* es = g_embed + (size_t)idx * Dn + t * 2;
    atomicAdd(es + 0, zv.x);
    atomicAdd(es + 1, zv.y);
    if (t == 0) {
        atomicAdd(&g_counts[idx], 1.0f);
        out[(size_t)Bn * Dn + row] = (float)idx;       // indices
    }
}

// ---------------------------------------------------------------------------
__global__ void ema_kernel(const float* __restrict__ ema_cs,
                           const float* __restrict__ ema_cb,
                           float* __restrict__ out) {
    const int k = blockIdx.x;
    const int t = threadIdx.x;

    const size_t offCb  = (size_t)Bn * Dn + Bn;
    const size_t offCs  = offCb + (size_t)Kn * Dn;
    const size_t offEma = offCs + Kn;

    float ncs = DECAYF * ema_cs[k] + OMDF * g_counts[k];
    float inv = 1.0f / (ncs + EPSF);
    if (t == 0) out[offCs + k] = ncs;

    float4 ev = ((const float4*)(ema_cb + (size_t)k * Dn))[t];
    float4 sv = ((const float4*)(g_embed + (size_t)k * Dn))[t];
    float4 ne;
    ne.x = DECAYF * ev.x + OMDF * sv.x;
    ne.y = DECAYF * ev.y + OMDF * sv.y;
    ne.z = DECAYF * ev.z + OMDF * sv.z;
    ne.w = DECAYF * ev.w + OMDF * sv.w;
    ((float4*)(out + offEma + (size_t)k * Dn))[t] = ne;
    float4 nc;
    nc.x = ne.x * inv; nc.y = ne.y * inv; nc.z = ne.z * inv; nc.w = ne.w * inv;
    ((float4*)(out + offCb + (size_t)k * Dn))[t] = nc;
}

// ---------------------------------------------------------------------------
extern "C" void kernel_launch(void* const* d_in, const int* in_sizes, int n_in,
                              void* d_out, int out_size) {
    const float* z_e    = (const float*)d_in[0];
    const float* cb     = (const float*)d_in[1];
    const float* ema_cs = (const float*)d_in[2];
    const float* ema_cb = (const float*)d_in[3];
    float* out = (float*)d_out;

    cudaFuncSetAttribute(gemm_kernel,
                         cudaFuncAttributeMaxDynamicSharedMemorySize, SMEM_BYTES);

    splitA_zero_kernel<<<4096, 256>>>(z_e);
    splitB_csq_kernel<<<Kn / 8, 256>>>(cb);
    gemm_kernel<<<(Bn / 128) * (Kn / 128), 256, SMEM_BYTES>>>();
    select_kernel<<<Bn, 256>>>(z_e, cb, out);
    ema_kernel<<<Kn, 128>>>(ema_cs, ema_cb, out);
}

// round 16
// speedup vs baseline: 1.0849x; 1.0849x over previous
#include <cuda_runtime.h>
#include <cuda_fp16.h>
#include <cstdint>

#define Bn 32768
#define Kn 8192
#define Dn 512
#define DECAYF 0.99f
#define OMDF   0.01f
#define EPSF   1e-5f

#define NITER 8              // K=512, BLK_K=64
#define STB 18432            // bytes per stage: 128 rows * 144B
#define SM_CSQ  110592       // after 3*STB*2
#define SMEM_BYTES 111104
#define STG_PITCH 144        // u8 staging row pitch (16B-aligned, 9-word stride)

// Device scratch (allocation-free). NEVER referenced from host code.
__device__ uint4  g_A4[(size_t)Bn * Dn * 2 / 16];     // fp16 of z_e
__device__ uint4  g_B4[(size_t)Kn * Dn * 2 / 16];     // fp16 of codebook
__device__ unsigned char g_scores8[(size_t)Bn * Kn];  // u8 score codes (step 2.0)
__device__ float  g_embed[(size_t)Kn * Dn];
__device__ float  g_counts[Kn];
__device__ float  g_csq[Kn];
__device__ unsigned g_cmax_bits;                      // max csq (float bits)

__device__ __forceinline__ uint32_t smem_u32(const void* p) {
    uint32_t a;
    asm("{ .reg .u64 t; cvta.to.shared.u64 t, %1; cvt.u32.u64 %0, t; }"
        : "=r"(a) : "l"(p));
    return a;
}
__device__ __forceinline__ void cpa16(uint32_t s, const void* g) {
    asm volatile("cp.async.cg.shared.global [%0], [%1], 16;" :: "r"(s), "l"(g));
}
#define CP_COMMIT() asm volatile("cp.async.commit_group;" ::: "memory")
#define CP_WAIT1()  asm volatile("cp.async.wait_group 1;" ::: "memory")

__device__ __forceinline__ void ldsm4(uint32_t& r0, uint32_t& r1, uint32_t& r2,
                                      uint32_t& r3, uint32_t addr) {
    asm volatile("ldmatrix.sync.aligned.m8n8.x4.shared.b16 {%0,%1,%2,%3}, [%4];"
                 : "=r"(r0), "=r"(r1), "=r"(r2), "=r"(r3) : "r"(addr));
}
// fp16-accumulator HMMA: D,C are 2x b32 (4 halves)
__device__ __forceinline__ void hmma16(uint32_t* c, uint32_t a0, uint32_t a1,
                                       uint32_t a2, uint32_t a3,
                                       uint32_t b0, uint32_t b1) {
    asm volatile(
        "mma.sync.aligned.m16n8k16.row.col.f16.f16.f16.f16 "
        "{%0,%1}, {%2,%3,%4,%5}, {%6,%7}, {%0,%1};"
        : "+r"(c[0]), "+r"(c[1])
        : "r"(a0), "r"(a1), "r"(a2), "r"(a3), "r"(b0), "r"(b1));
}
__device__ __forceinline__ unsigned f2ord(float f) {
    unsigned u = __float_as_uint(f);
    return (u & 0x80000000u) ? ~u : (u | 0x80000000u);
}
__device__ __forceinline__ void st16_cs(void* p, uint4 v) {
    asm volatile("st.global.cs.v4.u32 [%0], {%1,%2,%3,%4};"
                 :: "l"(p), "r"(v.x), "r"(v.y), "r"(v.z), "r"(v.w) : "memory");
}

// ---------------------------------------------------------------------------
// z_e fp32 -> fp16 conversion, FUSED with scratch zeroing
__global__ void splitA_zero_kernel(const float* __restrict__ src) {
    ushort4* dst = (ushort4*)(void*)g_A4;
    int stride = gridDim.x * blockDim.x;
    int t0 = blockIdx.x * blockDim.x + threadIdx.x;
    const int n4 = Bn * Dn / 4;
    for (int i = t0; i < n4; i += stride) {
        float4 v = ((const float4*)src)[i];
        __half2 lo = __floats2half2_rn(v.x, v.y);
        __half2 hi = __floats2half2_rn(v.z, v.w);
        ushort4 o;
        o.x = *(unsigned short*)&lo;  o.y = ((unsigned short*)&lo)[1];
        o.z = *(unsigned short*)&hi;  o.w = ((unsigned short*)&hi)[1];
        dst[i] = o;
    }
    const int N = Kn * Dn;
    for (int i = t0; i < N; i += stride) g_embed[i] = 0.0f;
    if (t0 < Kn) g_counts[t0] = 0.0f;
    if (t0 == 0) g_cmax_bits = 0u;
}

// codebook fp32 -> fp16 AND csq, one warp per row
__global__ void splitB_csq_kernel(const float* __restrict__ cb) {
    int warp = (blockIdx.x * blockDim.x + threadIdx.x) >> 5;
    int lane = threadIdx.x & 31;
    if (warp >= Kn) return;
    const float4* row = (const float4*)(cb + (size_t)warp * Dn);
    ushort4* drow = (ushort4*)((__half*)(void*)g_B4 + (size_t)warp * Dn);
    float s = 0.0f;
    #pragma unroll
    for (int i = lane; i < Dn / 4; i += 32) {
        float4 v = row[i];
        s += v.x * v.x + v.y * v.y + v.z * v.z + v.w * v.w;
        __half2 lo = __floats2half2_rn(v.x, v.y);
        __half2 hi = __floats2half2_rn(v.z, v.w);
        ushort4 o;
        o.x = *(unsigned short*)&lo;  o.y = ((unsigned short*)&lo)[1];
        o.z = *(unsigned short*)&hi;  o.w = ((unsigned short*)&hi)[1];
        drow[i] = o;
    }
    #pragma unroll
    for (int o = 16; o > 0; o >>= 1) s += __shfl_xor_sync(0xFFFFFFFFu, s, o);
    if (lane == 0) {
        g_csq[warp] = s;
        atomicMax(&g_cmax_bits, __float_as_uint(s));
    }
}

// ---------------------------------------------------------------------------
// Pass 1: fp16 GEMM (fp16 accumulate), u8 score codes -> smem stage -> DRAM.
// Block 128x128, 8 warps (4x2), warp tile 32x64, BLK_K=64, 3-slot cp.async.
// ---------------------------------------------------------------------------
__global__ void __launch_bounds__(256, 2)
gemm_kernel() {
    extern __shared__ char sm[];
    const uint32_t sA = smem_u32(sm);
    const uint32_t sB = sA + 3 * STB;
    float* csq_s = (float*)(sm + SM_CSQ);

    const int tid = threadIdx.x;
    const int lane = tid & 31;
    const int w = tid >> 5;
    const int warpM = w & 3;
    const int warpN = w >> 2;
    const int rowBase = (blockIdx.x >> 6) * 128;
    const int colBase = (blockIdx.x & 63) * 128;   // colTile-fastest: B L2-resident

    if (tid < 128) csq_s[tid] = g_csq[colBase + tid];

    const __half* A = (const __half*)(void*)g_A4;
    const __half* Bm = (const __half*)(void*)g_B4;

    const int lr = tid >> 3, lc = tid & 7;
    const uint32_t soBase = (uint32_t)(lr * 144 + lc * 16);
    const __half* gA = A + (size_t)(rowBase + lr) * Dn + lc * 8;
    const __half* gB = Bm + (size_t)(colBase + lr) * Dn + lc * 8;

    uint32_t acc[2][8][2];                 // fp16x2 accumulators
    #pragma unroll
    for (int mt = 0; mt < 2; mt++)
        #pragma unroll
        for (int nt = 0; nt < 8; nt++) { acc[mt][nt][0] = 0u; acc[mt][nt][1] = 0u; }

    const int lrow = lane & 15;
    const int khalf = lane >> 4;
    const uint32_t aRowOff = (uint32_t)((warpM * 32 + lrow) * 144 + khalf * 16);
    const uint32_t bRowOff = (uint32_t)((warpN * 64 + lrow) * 144 + khalf * 16);

    #define LOAD_STAGE(s, slot) do {                                           \
        int _off = (s) << 6;                                                   \
        uint32_t _da = sA + (slot) * STB;                                      \
        uint32_t _db = sB + (slot) * STB;                                      \
        _Pragma("unroll")                                                      \
        for (int it = 0; it < 4; it++) {                                       \
            uint32_t so = soBase + it * 32 * 144;                              \
            cpa16(_da + so, gA + (size_t)(it * 32) * Dn + _off);               \
            cpa16(_db + so, gB + (size_t)(it * 32) * Dn + _off);               \
        }                                                                      \
    } while (0)

    LOAD_STAGE(0, 0); CP_COMMIT();
    LOAD_STAGE(1, 1); CP_COMMIT();

    int slot = 0, nslot = 2;
    #pragma unroll 1
    for (int s = 0; s < NITER; s++) {
        CP_WAIT1();
        __syncthreads();
        if (s + 2 < NITER) LOAD_STAGE(s + 2, nslot);
        CP_COMMIT();

        const uint32_t da = sA + slot * STB;
        const uint32_t db = sB + slot * STB;
        #pragma unroll
        for (int k16 = 0; k16 < 4; k16++) {
            uint32_t a[2][4];
            #pragma unroll
            for (int mt = 0; mt < 2; mt++)
                ldsm4(a[mt][0], a[mt][1], a[mt][2], a[mt][3],
                      da + aRowOff + mt * 16 * 144 + k16 * 32);
            uint32_t b[4][4];
            #pragma unroll
            for (int np = 0; np < 4; np++)
                ldsm4(b[np][0], b[np][1], b[np][2], b[np][3],
                      db + bRowOff + np * 16 * 144 + k16 * 32);
            #pragma unroll
            for (int mt = 0; mt < 2; mt++)
                #pragma unroll
                for (int nt = 0; nt < 8; nt++)
                    hmma16(acc[mt][nt],
                           a[mt][0], a[mt][1], a[mt][2], a[mt][3],
                           b[nt >> 1][(nt & 1) ? 1 : 0],
                           b[nt >> 1][(nt & 1) ? 3 : 2]);
        }
        slot = slot == 2 ? 0 : slot + 1;
        nslot = nslot == 2 ? 0 : nslot + 1;
    }
    #undef LOAD_STAGE

    // epilogue: u8 code = clamp(round((csq - 2*dot)/2), 0, 255),
    // staged via smem (128 x 144B, 16B-aligned pitch), then coalesced 16B out.
    __syncthreads();                       // all warps done with stage buffers
    const int g = lane >> 2, tg = lane & 3;
    #pragma unroll
    for (int mt = 0; mt < 2; mt++) {
        #pragma unroll
        for (int half = 0; half < 2; half++) {
            int lrowE = warpM * 32 + mt * 16 + half * 8 + g;
            #pragma unroll
            for (int nt = 0; nt < 8; nt++) {
                int cl = warpN * 64 + nt * 8 + tg * 2;
                float2 f = __half22float2(*(const __half2*)&acc[mt][nt][half]);
                float s0 = fmaf(-2.0f, f.x, csq_s[cl]);
                float s1 = fmaf(-2.0f, f.y, csq_s[cl + 1]);
                int q0 = min(255, max(0, __float2int_rn(s0 * 0.5f)));
                int q1 = min(255, max(0, __float2int_rn(s1 * 0.5f)));
                *(unsigned short*)(sm + lrowE * STG_PITCH + cl) =
                    (unsigned short)(q0 | (q1 << 8));
            }
        }
    }
    __syncthreads();
    // coalesced copy-out: 128 rows x 128B as uint4 (4 per thread)
    unsigned char* dstBase = g_scores8 + (size_t)rowBase * Kn + colBase;
    #pragma unroll
    for (int it = 0; it < 4; it++) {
        int v = tid + (it << 8);
        int r = v >> 3, c = (v & 7) * 16;
        uint4 val = *(const uint4*)(sm + r * STG_PITCH + c);
        st16_cs(dstBase + (size_t)r * Kn + c, val);
    }
}

// ---------------------------------------------------------------------------
// Pass 2 (fused with scatter): u8 SIMD scan, exact fp32 rescore of candidates,
// write z_q + indices, atomic scatter counts/embed. One 256-thread block/row.
// ---------------------------------------------------------------------------
#define MAXCAND 128
__global__ void __launch_bounds__(256)
select_kernel(const float* __restrict__ z_e, const float* __restrict__ cb,
              float* __restrict__ out) {
    __shared__ float zs[Dn];
    __shared__ float rz[8];
    __shared__ int rsI[8];
    __shared__ int list[MAXCAND];
    __shared__ int cnt;
    __shared__ int thrS;
    __shared__ unsigned long long bestPk;

    const int row = blockIdx.x;
    const int t = threadIdx.x;
    const int lane = t & 31, wid = t >> 5;

    float2 zv = ((const float2*)(z_e + (size_t)row * Dn))[t];
    ((float2*)zs)[t] = zv;
    float zp = zv.x * zv.x + zv.y * zv.y;
    #pragma unroll
    for (int o = 16; o > 0; o >>= 1) zp += __shfl_xor_sync(0xFFFFFFFFu, zp, o);
    if (lane == 0) rz[wid] = zp;
    if (t == 0) { cnt = 0; bestPk = 0xFFFFFFFFFFFFFFFFull; }

    // load 32 u8 scores via 2 uint4 (evict-first), SIMD min
    const uint4* sr = (const uint4*)(g_scores8 + (size_t)row * Kn);
    uint4 sv[2];
    unsigned mn4 = 0xFFFFFFFFu;
    #pragma unroll
    for (int i = 0; i < 2; i++) {
        sv[i] = __ldcs(sr + t + (i << 8));
        mn4 = __vminu4(mn4, sv[i].x);
        mn4 = __vminu4(mn4, sv[i].y);
        mn4 = __vminu4(mn4, sv[i].z);
        mn4 = __vminu4(mn4, sv[i].w);
    }
    mn4 = __vminu4(mn4, mn4 >> 16);
    mn4 = __vminu4(mn4, mn4 >> 8);
    int mn = (int)(mn4 & 0xFFu);
    #pragma unroll
    for (int o = 16; o > 0; o >>= 1) mn = min(mn, __shfl_xor_sync(0xFFFFFFFFu, mn, o));
    if (lane == 0) rsI[wid] = mn;
    __syncthreads();
    if (t == 0) {
        float zsq = 0.0f;
        int m = 255;
        #pragma unroll
        for (int i = 0; i < 8; i++) { zsq += rz[i]; m = min(m, rsI[i]); }
        float cmax = __uint_as_float(g_cmax_bits);
        // margin (float) = h0 bound + fp16-acc slack; +2 units for u8 rounding
        float E = 0.001953125f * sqrtf(zsq * cmax) + 16.0f;
        thrS = m + (int)ceilf(E * 0.5f) + 2;
    }
    __syncthreads();

    const int thrU = thrS;
    if (thrU <= 254) {
        const unsigned thrPack = (unsigned)thrU * 0x01010101u;
        #pragma unroll
        for (int i = 0; i < 2; i++) {
            const unsigned* uw = (const unsigned*)&sv[i];
            #pragma unroll
            for (int wv = 0; wv < 4; wv++) {
                unsigned mask = __vcmpleu4(uw[wv], thrPack);
                if (mask) {
                    int base = (i << 12) + t * 16 + wv * 4;
                    #pragma unroll
                    for (int j = 0; j < 4; j++) {
                        if (mask & (0xFFu << (8 * j))) {
                            int p = atomicAdd(&cnt, 1);
                            if (p < MAXCAND) list[p] = base + j;
                        }
                    }
                }
            }
        }
        __syncthreads();
    } else {
        if (t == 0) cnt = MAXCAND + 1;     // force brute-force fallback
        __syncthreads();
    }

    if (cnt <= MAXCAND) {
        const int n = cnt;
        for (int j = wid; j < n; j += 8) {
            const int k = list[j];
            const float4* crow = (const float4*)(cb + (size_t)k * Dn);
            const float4* zrow = (const float4*)zs;
            float d = 0.0f;
            #pragma unroll
            for (int c = lane; c < Dn / 4; c += 32) {
                float4 aa = zrow[c], bb = crow[c];
                d += aa.x * bb.x + aa.y * bb.y + aa.z * bb.z + aa.w * bb.w;
            }
            #pragma unroll
            for (int o = 16; o > 0; o >>= 1) d += __shfl_xor_sync(0xFFFFFFFFu, d, o);
            if (lane == 0) {
                float ex = fmaf(-2.0f, d, g_csq[k]);
                unsigned long long pk =
                    ((unsigned long long)f2ord(ex) << 32) | (unsigned)k;
                atomicMin(&bestPk, pk);
            }
        }
    } else {
        // pathological overflow: exact brute force (sound fallback)
        for (int k = t; k < Kn; k += 256) {
            const float* crow = cb + (size_t)k * Dn;
            float d = 0.0f;
            for (int c = 0; c < Dn; c++) d += zs[c] * crow[c];
            float ex = fmaf(-2.0f, d, g_csq[k]);
            unsigned long long pk =
                ((unsigned long long)f2ord(ex) << 32) | (unsigned)k;
            atomicMin(&bestPk, pk);
        }
    }
    __syncthreads();

    const int idx = (int)(unsigned)(bestPk & 0xFFFFFFFFull);
    float2 cq = ((const float2*)(cb + (size_t)idx * Dn))[t];
    ((float2*)(out + (size_t)row * Dn))[t] = cq;       // z_q
    float* es = g_embed + (size_t)idx * Dn + t * 2;
    atomicAdd(es + 0, zv.x);
    atomicAdd(es + 1, zv.y);
    if (t == 0) {
        atomicAdd(&g_counts[idx], 1.0f);
        out[(size_t)Bn * Dn + row] = (float)idx;       // indices
    }
}

// ---------------------------------------------------------------------------
__global__ void ema_kernel(const float* __restrict__ ema_cs,
                           const float* __restrict__ ema_cb,
                           float* __restrict__ out) {
    const int k = blockIdx.x;
    const int t = threadIdx.x;

    const size_t offCb  = (size_t)Bn * Dn + Bn;
    const size_t offCs  = offCb + (size_t)Kn * Dn;
    const size_t offEma = offCs + Kn;

    float ncs = DECAYF * ema_cs[k] + OMDF * g_counts[k];
    float inv = 1.0f / (ncs + EPSF);
    if (t == 0) out[offCs + k] = ncs;

    float4 ev = ((const float4*)(ema_cb + (size_t)k * Dn))[t];
    float4 sv = ((const float4*)(g_embed + (size_t)k * Dn))[t];
    float4 ne;
    ne.x = DECAYF * ev.x + OMDF * sv.x;
    ne.y = DECAYF * ev.y + OMDF * sv.y;
    ne.z = DECAYF * ev.z + OMDF * sv.z;
    ne.w = DECAYF * ev.w + OMDF * sv.w;
    ((float4*)(out + offEma + (size_t)k * Dn))[t] = ne;
    float4 nc;
    nc.x = ne.x * inv; nc.y = ne.y * inv; nc.z = ne.z * inv; nc.w = ne.w * inv;
    ((float4*)(out + offCb + (size_t)k * Dn))[t] = nc;
}

// ---------------------------------------------------------------------------
extern "C" void kernel_launch(void* const* d_in, const int* in_sizes, int n_in,
                              void* d_out, int out_size) {
    const float* z_e    = (const float*)d_in[0];
    const float* cb     = (const float*)d_in[1];
    const float* ema_cs = (const float*)d_in[2];
    const float* ema_cb = (const float*)d_in[3];
    float* out = (float*)d_out;

    cudaFuncSetAttribute(gemm_kernel,
                         cudaFuncAttributeMaxDynamicSharedMemorySize, SMEM_BYTES);

    splitA_zero_kernel<<<4096, 256>>>(z_e);
    splitB_csq_kernel<<<Kn / 8, 256>>>(cb);
    gemm_kernel<<<(Bn / 128) * (Kn / 128), 256, SMEM_BYTES>>>();
    select_kernel<<<Bn, 256>>>(z_e, cb, out);
    ema_kernel<<<Kn, 128>>>(ema_cs, ema_cb, out);
}